// round 13
// baseline (speedup 1.0000x reference)
#include <cuda_runtime.h>
#include <cuda_fp16.h>
#include <math.h>
#include <stdint.h>

// Problem constants
#define NTOK 4096
#define DDIM 1024
#define HDIM 4096
#define NEXP 8
#define CAP  4096
#define NSLOT (NTOK*2)

// fp16 GEMM tiling: block 128x128, warp 64x32 (2x4 warps), K-chunk 64 (128B rows)
#define TM 128
#define TN 128
#define BKH 64
#define NPIPE 3
#define ASTAGE_B (TM*128)
#define BSTAGE_B (TN*128)
#define STAGE_B  (ASTAGE_B+BSTAGE_B)
#define SMEM_BYTES (NPIPE*STAGE_B)   // 98304 B -> 2 CTAs/SM

// ---------------- scratch ----------------------------------------------------
__device__ int    g_cnt[NEXP];
__device__ int    g_etok[NEXP * CAP];
__device__ float  g_egate[NEXP * CAP];
__device__ __half g_xh[(size_t)NTOK * DDIM];
__device__ __half g_w1h[(size_t)NEXP * HDIM * DDIM];
__device__ __half g_w2h[(size_t)NEXP * DDIM * HDIM];
__device__ __half g_h[(size_t)NSLOT * HDIM];
__device__ float  g_ypart[(size_t)2 * NSLOT * DDIM];

// ---------------- helpers ----------------------------------------------------
__device__ __forceinline__ uint32_t smem_u32(const void* p) {
    uint32_t a;
    asm("{ .reg .u64 t; cvta.to.shared.u64 t, %1; cvt.u32.u64 %0, t; }"
        : "=r"(a) : "l"(p));
    return a;
}
__device__ __forceinline__ void mma16816(float c[4], const unsigned a[4],
                                         const unsigned b[2]) {
    asm volatile(
        "mma.sync.aligned.m16n8k16.row.col.f32.f16.f16.f32 "
        "{%0,%1,%2,%3}, {%4,%5,%6,%7}, {%8,%9}, {%0,%1,%2,%3};"
        : "+f"(c[0]), "+f"(c[1]), "+f"(c[2]), "+f"(c[3])
        : "r"(a[0]), "r"(a[1]), "r"(a[2]), "r"(a[3]), "r"(b[0]), "r"(b[1]));
}
#define LDSM_X4(r0, r1, r2, r3, addr)                                        \
    asm volatile("ldmatrix.sync.aligned.m8n8.x4.shared.b16 {%0,%1,%2,%3}, [%4];" \
                 : "=r"(r0), "=r"(r1), "=r"(r2), "=r"(r3) : "r"(addr))
#define CPASYNC16(dst, src) \
    asm volatile("cp.async.cg.shared.global [%0], [%1], 16;" \
                 :: "r"(dst), "l"(src) : "memory")
#define CP_COMMIT() asm volatile("cp.async.commit_group;" ::: "memory")
#define CP_WAIT(n)  asm volatile("cp.async.wait_group %0;" :: "n"(n) : "memory")

// convert 16 fp32 -> 16 fp16 (two 16B stores)
__device__ __forceinline__ void cvt16(const float* __restrict__ src,
                                      __half* __restrict__ dst) {
    const float4* s4 = (const float4*)src;
    float4 a0 = s4[0], a1 = s4[1], a2 = s4[2], a3 = s4[3];
    __half2 q0 = __floats2half2_rn(a0.x, a0.y), q1 = __floats2half2_rn(a0.z, a0.w);
    __half2 q2 = __floats2half2_rn(a1.x, a1.y), q3 = __floats2half2_rn(a1.z, a1.w);
    __half2 q4 = __floats2half2_rn(a2.x, a2.y), q5 = __floats2half2_rn(a2.z, a2.w);
    __half2 q6 = __floats2half2_rn(a3.x, a3.y), q7 = __floats2half2_rn(a3.z, a3.w);
    uint4 u0, u1;
    u0.x = *(uint32_t*)&q0; u0.y = *(uint32_t*)&q1;
    u0.z = *(uint32_t*)&q2; u0.w = *(uint32_t*)&q3;
    u1.x = *(uint32_t*)&q4; u1.y = *(uint32_t*)&q5;
    u1.z = *(uint32_t*)&q6; u1.w = *(uint32_t*)&q7;
    ((uint4*)dst)[0] = u0;
    ((uint4*)dst)[1] = u1;
}

// ---------------- small kernels ----------------------------------------------
__global__ void init_kernel() {
    if (threadIdx.x < NEXP) g_cnt[threadIdx.x] = 0;
}

// ---------------- router (fp32-exact) + x->fp16 + W1->fp16 -------------------
__global__ __launch_bounds__(256) void router_kernel(
    const float* __restrict__ x, const float* __restrict__ Wr,
    const float* __restrict__ br, const float* __restrict__ W1) {
    __shared__ float sWr[NEXP * DDIM];
    int tid = threadIdx.x;
    for (int i = tid; i < NEXP * DDIM; i += 256) sWr[i] = Wr[i];
    __syncthreads();
    int warp = tid >> 5, lane = tid & 31;
    int tok = blockIdx.x * 8 + warp;
    {
        const float* xr = x + (size_t)tok * DDIM;
        __half* xo = g_xh + (size_t)tok * DDIM;
        float acc[NEXP];
#pragma unroll
        for (int e = 0; e < NEXP; e++) acc[e] = 0.f;
#pragma unroll
        for (int i = 0; i < DDIM / 128; i++) {
            int d = i * 128 + lane * 4;
            float4 xv = *(const float4*)(xr + d);
            __half2 h0 = __floats2half2_rn(xv.x, xv.y);
            __half2 h1 = __floats2half2_rn(xv.z, xv.w);
            uint2 u;
            u.x = *(uint32_t*)&h0; u.y = *(uint32_t*)&h1;
            *(uint2*)(xo + d) = u;
#pragma unroll
            for (int e = 0; e < NEXP; e++) {
                const float* w = sWr + e * DDIM + d;
                acc[e] += xv.x * w[0] + xv.y * w[1] + xv.z * w[2] + xv.w * w[3];
            }
        }
#pragma unroll
        for (int e = 0; e < NEXP; e++)
#pragma unroll
            for (int o = 16; o > 0; o >>= 1)
                acc[e] += __shfl_down_sync(0xffffffffu, acc[e], o);
        if (lane == 0) {
            float v0 = -3.4e38f, v1 = -3.4e38f;
            int i0 = 0, i1 = 0;
#pragma unroll
            for (int e = 0; e < NEXP; e++) {
                float l = acc[e] + br[e];
                if (l > v0) { v1 = v0; i1 = i0; v0 = l; i0 = e; }
                else if (l > v1) { v1 = l; i1 = e; }
            }
            float t = expf(v1 - v0);
            float inv = 1.f / (1.f + t);
            int p0 = atomicAdd(&g_cnt[i0], 1);
            g_etok[i0 * CAP + p0] = tok * 2;
            g_egate[i0 * CAP + p0] = inv;
            int p1 = atomicAdd(&g_cnt[i1], 1);
            g_etok[i1 * CAP + p1] = tok * 2 + 1;
            g_egate[i1 * CAP + p1] = t * inv;
        }
    }
    // ---- W1 fp32->fp16: 65536 elems per CTA (16 x 16 elems per thread) ----
    {
        size_t cbase = (size_t)blockIdx.x * 65536 + (size_t)tid * 16;
#pragma unroll 4
        for (int j = 0; j < 16; j++) {
            size_t idx = cbase + (size_t)j * 4096;
            cvt16(W1 + idx, g_w1h + idx);
        }
    }
}

// ---------------- fp16 grouped GEMM (R6 config: 8 warps, warp tile 64x32) -----
// MODE 1: g_h(fp16) = relu(gather(g_xh) @ g_w1h[e]^T + b1[e])   KITER=16, kz=0
//         + each CTA converts a 4096-elem slice of W2 (hidden under pipeline)
// MODE 2: ypart[kz] = gate*(g_h @ g_w2h[e]^T [+ b2])            KITER=32, kz=0,1
template <int KITER, int MODE>
__global__ __launch_bounds__(256, 2) void moe_hgemm(
    const __half* __restrict__ Ah, const __half* __restrict__ Bh,
    const float* __restrict__ bias,
    const float* __restrict__ csrc, __half* __restrict__ cdst) {
    const int NTOT = (MODE == 1) ? HDIM : DDIM;
    const int KFULL = (MODE == 1) ? DDIM : HDIM;
    int tid = threadIdx.x;

    // ---- embedded W2 convert (MODE 1 only): before any early exit ----
    if (MODE == 1) {
        size_t cta = ((size_t)blockIdx.z * gridDim.y + blockIdx.y) * gridDim.x +
                     blockIdx.x;                       // 0..8191
        size_t cb = cta * 4096 + (size_t)tid * 16;     // 8192*4096 = 33.55M
        cvt16(csrc + cb, cdst + cb);
    }

    int z = blockIdx.z;
    int e = z & 7, kz = (MODE == 2) ? (z >> 3) : 0;
    int cnt = g_cnt[e];
    int m0 = blockIdx.y * TM;
    if (m0 >= cnt) return;
    int n0 = blockIdx.x * TN;
    int off = 0;
#pragma unroll
    for (int q = 0; q < NEXP; q++) off += (q < e) ? g_cnt[q] : 0;
    int k0g = kz * (KITER * BKH);

    extern __shared__ __align__(1024) char sm[];
    __shared__ int sRow[TM];
    __shared__ float sGate[TM];

    for (int r = tid; r < TM; r += 256) {
        int slot = m0 + r;
        if (MODE == 1) {
            sRow[r] = (slot < cnt) ? (g_etok[e * CAP + slot] >> 1) : 0;
        } else {
            sRow[r] = (slot < cnt) ? g_etok[e * CAP + slot] : 0;
            sGate[r] = (slot < cnt) ? g_egate[e * CAP + slot] : 0.f;
        }
    }
    __syncthreads();

    // ---- producer mapping: thread -> (row = tid/2, 4 of 8 16B chunks) ----
    int prow = tid >> 1;
    int c0 = (tid & 1) * 4;
    int psw = prow & 7;
    const __half* aRow;
    if (MODE == 1) {
        aRow = Ah + (size_t)sRow[prow] * KFULL + k0g;
    } else {
        int sg = off + m0 + prow;
        if (sg > NSLOT - 1) sg = NSLOT - 1;
        aRow = g_h + (size_t)sg * KFULL + k0g;
    }
    const __half* bRow = Bh + (size_t)e * NTOT * KFULL +
                         (size_t)(n0 + prow) * KFULL + k0g;
    uint32_t sb = smem_u32(sm);
    uint32_t aDstBase = sb + prow * 128;
    uint32_t bDstBase = sb + ASTAGE_B + prow * 128;

#define ISSUE(c)                                                      \
    {                                                                 \
        uint32_t so_ = ((c) % NPIPE) * STAGE_B;                       \
        const __half* ag_ = aRow + (c)*BKH;                           \
        const __half* bg_ = bRow + (c)*BKH;                           \
        _Pragma("unroll")                                             \
        for (int j = 0; j < 4; j++) {                                 \
            int cc = c0 + j;                                          \
            int sc = cc ^ psw;                                        \
            CPASYNC16(aDstBase + so_ + sc * 16, ag_ + cc * 8);        \
            CPASYNC16(bDstBase + so_ + sc * 16, bg_ + cc * 8);        \
        }                                                             \
    }

#pragma unroll
    for (int c = 0; c < NPIPE - 1; c++) {
        ISSUE(c);
        CP_COMMIT();
    }

    // ---- consumer mapping: 8 warps = 2(m) x 4(n), warp tile 64x32 ----
    int lane = tid & 31, wid = tid >> 5;
    int wm = wid >> 2, wn = wid & 3;
    int s = lane & 7;
    int aChunkBit = lane >> 4;
    uint32_t aByte = (uint32_t)(wm * 64 + (lane & 7) + ((lane >> 3) & 1) * 8) * 128;
    int bChunkBit = (lane >> 3) & 1;
    uint32_t bByte = ASTAGE_B +
                     (uint32_t)(wn * 32 + ((lane >> 4) & 1) * 8 + (lane & 7)) * 128;

    float acc[4][4][4];
#pragma unroll
    for (int mt = 0; mt < 4; mt++)
#pragma unroll
        for (int nt = 0; nt < 4; nt++)
#pragma unroll
            for (int v = 0; v < 4; v++) acc[mt][nt][v] = 0.f;

    for (int c = 0; c < KITER; c++) {
        CP_WAIT(NPIPE - 2);
        __syncthreads();
        if (c + NPIPE - 1 < KITER) ISSUE(c + NPIPE - 1);
        CP_COMMIT();

        uint32_t stb = sb + (c % NPIPE) * STAGE_B;
#pragma unroll
        for (int kt = 0; kt < 4; kt++) {
            unsigned af[4][4], bf[4][2];
#pragma unroll
            for (int mt = 0; mt < 4; mt++) {
                uint32_t ad = stb + aByte + mt * 2048 +
                              (uint32_t)(((2 * kt + aChunkBit) ^ s) << 4);
                LDSM_X4(af[mt][0], af[mt][1], af[mt][2], af[mt][3], ad);
            }
#pragma unroll
            for (int p = 0; p < 2; p++) {
                uint32_t bd = stb + bByte + p * 2048 +
                              (uint32_t)(((2 * kt + bChunkBit) ^ s) << 4);
                LDSM_X4(bf[2 * p][0], bf[2 * p][1], bf[2 * p + 1][0],
                        bf[2 * p + 1][1], bd);
            }
#pragma unroll
            for (int mt = 0; mt < 4; mt++)
#pragma unroll
                for (int nt = 0; nt < 4; nt++)
                    mma16816(acc[mt][nt], af[mt], bf[nt]);
        }
    }
#undef ISSUE

    // ---- epilogue ----
    int g = lane >> 2, tig = lane & 3;
#pragma unroll
    for (int mt = 0; mt < 4; mt++) {
#pragma unroll
        for (int hh = 0; hh < 2; hh++) {
            int r = wm * 64 + mt * 16 + g + 8 * hh;
            int slot = m0 + r;
            if (slot >= cnt) continue;
            if (MODE == 1) {
                __half* orow = g_h + (size_t)(off + slot) * HDIM + n0;
                const float* bp = bias + e * HDIM + n0;
#pragma unroll
                for (int nt = 0; nt < 4; nt++) {
                    int col = wn * 32 + nt * 8 + 2 * tig;
                    float v0 = fmaxf(acc[mt][nt][hh * 2 + 0] + bp[col], 0.f);
                    float v1 = fmaxf(acc[mt][nt][hh * 2 + 1] + bp[col + 1], 0.f);
                    __half2 hv = __floats2half2_rn(v0, v1);
                    *(__half2*)(orow + col) = hv;
                }
            } else {
                int packed = sRow[r];
                float gte = sGate[r];
                float* orow = g_ypart + ((size_t)kz * NSLOT + packed) * DDIM + n0;
                const float* bp = bias + e * DDIM + n0;
#pragma unroll
                for (int nt = 0; nt < 4; nt++) {
                    int col = wn * 32 + nt * 8 + 2 * tig;
                    float v0 = acc[mt][nt][hh * 2 + 0];
                    float v1 = acc[mt][nt][hh * 2 + 1];
                    if (kz == 0) { v0 += bp[col]; v1 += bp[col + 1]; }
                    *(float2*)(orow + col) = make_float2(v0 * gte, v1 * gte);
                }
            }
        }
    }
}

// ---------------- combine: sum 2 k-choices x 2 K-splits -----------------------
__global__ void combine_kernel(float* __restrict__ out) {
    int i = blockIdx.x * blockDim.x + threadIdx.x;
    const int TOT = NTOK * DDIM / 4;
    if (i >= TOT) return;
    int n = i / (DDIM / 4);
    int dg = i % (DDIM / 4);
    const float4* yp = (const float4*)g_ypart;
    const size_t RP = DDIM / 4;
    float4 a0 = yp[(size_t)(2 * n) * RP + dg];
    float4 a1 = yp[(size_t)(2 * n + 1) * RP + dg];
    float4 b0 = yp[((size_t)NSLOT + 2 * n) * RP + dg];
    float4 b1 = yp[((size_t)NSLOT + 2 * n + 1) * RP + dg];
    float4 r;
    r.x = (a0.x + b0.x) + (a1.x + b1.x);
    r.y = (a0.y + b0.y) + (a1.y + b1.y);
    r.z = (a0.z + b0.z) + (a1.z + b1.z);
    r.w = (a0.w + b0.w) + (a1.w + b1.w);
    ((float4*)out)[i] = r;
}

// ---------------- launch (single stream, converts hidden in-kernel) ----------
extern "C" void kernel_launch(void* const* d_in, const int* in_sizes, int n_in,
                              void* d_out, int out_size) {
    const float* x  = (const float*)d_in[0];
    const float* Wr = (const float*)d_in[1];
    const float* br = (const float*)d_in[2];
    const float* W1 = (const float*)d_in[3];
    const float* b1 = (const float*)d_in[4];
    const float* W2 = (const float*)d_in[5];
    const float* b2 = (const float*)d_in[6];
    float* out = (float*)d_out;
    (void)in_sizes; (void)n_in; (void)out_size;

    cudaFuncSetAttribute(moe_hgemm<16, 1>,
                         cudaFuncAttributeMaxDynamicSharedMemorySize, SMEM_BYTES);
    cudaFuncSetAttribute(moe_hgemm<32, 2>,
                         cudaFuncAttributeMaxDynamicSharedMemorySize, SMEM_BYTES);

    __half *xh, *w1h, *w2h;
    cudaGetSymbolAddress((void**)&xh, g_xh);
    cudaGetSymbolAddress((void**)&w1h, g_w1h);
    cudaGetSymbolAddress((void**)&w2h, g_w2h);

    init_kernel<<<1, 32>>>();

    // router + x->fp16 + W1->fp16 in one DRAM-bound kernel
    router_kernel<<<NTOK / 8, 256>>>(x, Wr, br, W1);

    // GEMM1 (also converts W2 -> fp16, hidden under its idle DRAM)
    dim3 g1(HDIM / TN, NTOK / TM, NEXP);        // 32 x 32 x 8 = 8192 CTAs
    moe_hgemm<16, 1><<<g1, 256, SMEM_BYTES>>>(xh, w1h, b1, W2, w2h);

    // GEMM2 (split-K=2)
    dim3 g2(DDIM / TN, NTOK / TM, NEXP * 2);    // 8 x 32 x 16
    moe_hgemm<32, 2><<<g2, 256, SMEM_BYTES>>>(nullptr, w2h, b2, nullptr, nullptr);

    combine_kernel<<<(NTOK * DDIM / 4 + 255) / 256, 256>>>(out);
}

// round 15
// speedup vs baseline: 1.4952x; 1.4952x over previous
#include <cuda_runtime.h>
#include <cuda_fp16.h>
#include <math.h>
#include <stdint.h>

// Problem constants
#define NTOK 4096
#define DDIM 1024
#define HDIM 4096
#define NEXP 8
#define CAP  4096
#define NSLOT (NTOK*2)

// fp16 GEMM tiling: block 128x128, warp 64x32 (2x4 warps), K-chunk 64 (128B rows)
#define TM 128
#define TN 128
#define BKH 64
#define NPIPE 3
#define ASTAGE_B (TM*128)
#define BSTAGE_B (TN*128)
#define STAGE_B  (ASTAGE_B+BSTAGE_B)
#define SMEM_BYTES (NPIPE*STAGE_B)   // 98304 B -> 2 CTAs/SM

// ---------------- scratch ----------------------------------------------------
__device__ int    g_cnt[NEXP];
__device__ int    g_etok[NEXP * CAP];
__device__ float  g_egate[NEXP * CAP];
__device__ __half g_xh[(size_t)NTOK * DDIM];
__device__ __half g_w1h[(size_t)NEXP * HDIM * DDIM];
__device__ __half g_w2h[(size_t)NEXP * DDIM * HDIM];
__device__ __half g_h[(size_t)NSLOT * HDIM];

// ---------------- helpers ----------------------------------------------------
__device__ __forceinline__ uint32_t smem_u32(const void* p) {
    uint32_t a;
    asm("{ .reg .u64 t; cvta.to.shared.u64 t, %1; cvt.u32.u64 %0, t; }"
        : "=r"(a) : "l"(p));
    return a;
}
__device__ __forceinline__ void mma16816(float c[4], const unsigned a[4],
                                         const unsigned b[2]) {
    asm volatile(
        "mma.sync.aligned.m16n8k16.row.col.f32.f16.f16.f32 "
        "{%0,%1,%2,%3}, {%4,%5,%6,%7}, {%8,%9}, {%0,%1,%2,%3};"
        : "+f"(c[0]), "+f"(c[1]), "+f"(c[2]), "+f"(c[3])
        : "r"(a[0]), "r"(a[1]), "r"(a[2]), "r"(a[3]), "r"(b[0]), "r"(b[1]));
}
#define LDSM_X4(r0, r1, r2, r3, addr)                                        \
    asm volatile("ldmatrix.sync.aligned.m8n8.x4.shared.b16 {%0,%1,%2,%3}, [%4];" \
                 : "=r"(r0), "=r"(r1), "=r"(r2), "=r"(r3) : "r"(addr))
#define CPASYNC16(dst, src) \
    asm volatile("cp.async.cg.shared.global [%0], [%1], 16;" \
                 :: "r"(dst), "l"(src) : "memory")
#define CP_COMMIT() asm volatile("cp.async.commit_group;" ::: "memory")
#define CP_WAIT(n)  asm volatile("cp.async.wait_group %0;" :: "n"(n) : "memory")
#define REDADD(ptr, v) \
    asm volatile("red.global.add.f32 [%0], %1;" :: "l"(ptr), "f"(v) : "memory")

// ---------------- cvt kernels -------------------------------------------------
// INIT=1: also zeroes g_cnt. ZOUT: also zeroes zbuf[0..nz4) as float4.
template <int INIT>
__global__ __launch_bounds__(256) void cvt_kernel(const float* __restrict__ in,
                                                  __half* __restrict__ out,
                                                  int n8,
                                                  float* __restrict__ zbuf,
                                                  int nz4) {
    int i = blockIdx.x * 256 + threadIdx.x;
    if (INIT && i < NEXP) g_cnt[i] = 0;
    if (zbuf != nullptr && i < nz4)
        ((float4*)zbuf)[i] = make_float4(0.f, 0.f, 0.f, 0.f);
    if (i >= n8) return;
    size_t base = (size_t)i * 8;
    float4 v0 = *(const float4*)(in + base);
    float4 v1 = *(const float4*)(in + base + 4);
    __half2 h0 = __floats2half2_rn(v0.x, v0.y);
    __half2 h1 = __floats2half2_rn(v0.z, v0.w);
    __half2 h2 = __floats2half2_rn(v1.x, v1.y);
    __half2 h3 = __floats2half2_rn(v1.z, v1.w);
    uint4 u;
    u.x = *(uint32_t*)&h0; u.y = *(uint32_t*)&h1;
    u.z = *(uint32_t*)&h2; u.w = *(uint32_t*)&h3;
    *(uint4*)(out + base) = u;
}

// ---------------- router (fp32-exact) + x->fp16 convert -----------------------
__global__ __launch_bounds__(256) void router_kernel(
    const float* __restrict__ x, const float* __restrict__ Wr,
    const float* __restrict__ br) {
    __shared__ float sWr[NEXP * DDIM];
    int tid = threadIdx.x;
    for (int i = tid; i < NEXP * DDIM; i += 256) sWr[i] = Wr[i];
    __syncthreads();
    int warp = tid >> 5, lane = tid & 31;
    int tok = blockIdx.x * 8 + warp;
    if (tok >= NTOK) return;
    const float* xr = x + (size_t)tok * DDIM;
    __half* xo = g_xh + (size_t)tok * DDIM;
    float acc[NEXP];
#pragma unroll
    for (int e = 0; e < NEXP; e++) acc[e] = 0.f;
#pragma unroll
    for (int i = 0; i < DDIM / 128; i++) {
        int d = i * 128 + lane * 4;
        float4 xv = *(const float4*)(xr + d);
        __half2 h0 = __floats2half2_rn(xv.x, xv.y);
        __half2 h1 = __floats2half2_rn(xv.z, xv.w);
        uint2 u;
        u.x = *(uint32_t*)&h0; u.y = *(uint32_t*)&h1;
        *(uint2*)(xo + d) = u;
#pragma unroll
        for (int e = 0; e < NEXP; e++) {
            const float* w = sWr + e * DDIM + d;
            acc[e] += xv.x * w[0] + xv.y * w[1] + xv.z * w[2] + xv.w * w[3];
        }
    }
#pragma unroll
    for (int e = 0; e < NEXP; e++)
#pragma unroll
        for (int o = 16; o > 0; o >>= 1)
            acc[e] += __shfl_down_sync(0xffffffffu, acc[e], o);
    if (lane == 0) {
        float v0 = -3.4e38f, v1 = -3.4e38f;
        int i0 = 0, i1 = 0;
#pragma unroll
        for (int e = 0; e < NEXP; e++) {
            float l = acc[e] + br[e];
            if (l > v0) { v1 = v0; i1 = i0; v0 = l; i0 = e; }
            else if (l > v1) { v1 = l; i1 = e; }
        }
        float t = expf(v1 - v0);
        float inv = 1.f / (1.f + t);
        int p0 = atomicAdd(&g_cnt[i0], 1);
        g_etok[i0 * CAP + p0] = tok * 2;
        g_egate[i0 * CAP + p0] = inv;
        int p1 = atomicAdd(&g_cnt[i1], 1);
        g_etok[i1 * CAP + p1] = tok * 2 + 1;
        g_egate[i1 * CAP + p1] = t * inv;
    }
}

// ---------------- fp16 grouped GEMM (R6 config: 8 warps, warp tile 64x32) -----
// MODE 1: g_h(fp16) = relu(gather(g_xh) @ g_w1h[e]^T + b1[e])   KITER=16, kz=0
// MODE 2: out += gate*(g_h @ g_w2h[e]^T [+ b2]) via red.global  KITER=32, kz=0,1
template <int KITER, int MODE>
__global__ __launch_bounds__(256, 2) void moe_hgemm(
    const __half* __restrict__ Ah, const __half* __restrict__ Bh,
    const float* __restrict__ bias, float* __restrict__ outp) {
    const int NTOT = (MODE == 1) ? HDIM : DDIM;
    const int KFULL = (MODE == 1) ? DDIM : HDIM;
    int z = blockIdx.z;
    int e = z & 7, kz = (MODE == 2) ? (z >> 3) : 0;
    int cnt = g_cnt[e];
    int m0 = blockIdx.y * TM;
    if (m0 >= cnt) return;
    int n0 = blockIdx.x * TN;
    int off = 0;
#pragma unroll
    for (int q = 0; q < NEXP; q++) off += (q < e) ? g_cnt[q] : 0;
    int k0g = kz * (KITER * BKH);

    extern __shared__ __align__(1024) char sm[];
    __shared__ int sRow[TM];
    __shared__ float sGate[TM];

    int tid = threadIdx.x;
    for (int r = tid; r < TM; r += 256) {
        int slot = m0 + r;
        if (MODE == 1) {
            sRow[r] = (slot < cnt) ? (g_etok[e * CAP + slot] >> 1) : 0;
        } else {
            sRow[r] = (slot < cnt) ? g_etok[e * CAP + slot] : 0;
            sGate[r] = (slot < cnt) ? g_egate[e * CAP + slot] : 0.f;
        }
    }
    __syncthreads();

    // ---- producer mapping: thread -> (row = tid/2, 4 of 8 16B chunks) ----
    int prow = tid >> 1;
    int c0 = (tid & 1) * 4;
    int psw = prow & 7;
    const __half* aRow;
    if (MODE == 1) {
        aRow = Ah + (size_t)sRow[prow] * KFULL + k0g;
    } else {
        int sg = off + m0 + prow;
        if (sg > NSLOT - 1) sg = NSLOT - 1;
        aRow = g_h + (size_t)sg * KFULL + k0g;
    }
    const __half* bRow = Bh + (size_t)e * NTOT * KFULL +
                         (size_t)(n0 + prow) * KFULL + k0g;
    uint32_t sb = smem_u32(sm);
    uint32_t aDstBase = sb + prow * 128;
    uint32_t bDstBase = sb + ASTAGE_B + prow * 128;

#define ISSUE(c)                                                      \
    {                                                                 \
        uint32_t so_ = ((c) % NPIPE) * STAGE_B;                       \
        const __half* ag_ = aRow + (c)*BKH;                           \
        const __half* bg_ = bRow + (c)*BKH;                           \
        _Pragma("unroll")                                             \
        for (int j = 0; j < 4; j++) {                                 \
            int cc = c0 + j;                                          \
            int sc = cc ^ psw;                                        \
            CPASYNC16(aDstBase + so_ + sc * 16, ag_ + cc * 8);        \
            CPASYNC16(bDstBase + so_ + sc * 16, bg_ + cc * 8);        \
        }                                                             \
    }

#pragma unroll
    for (int c = 0; c < NPIPE - 1; c++) {
        ISSUE(c);
        CP_COMMIT();
    }

    // ---- consumer mapping: 8 warps = 2(m) x 4(n), warp tile 64x32 ----
    int lane = tid & 31, wid = tid >> 5;
    int wm = wid >> 2, wn = wid & 3;
    int s = lane & 7;
    int aChunkBit = lane >> 4;
    uint32_t aByte = (uint32_t)(wm * 64 + (lane & 7) + ((lane >> 3) & 1) * 8) * 128;
    int bChunkBit = (lane >> 3) & 1;
    uint32_t bByte = ASTAGE_B +
                     (uint32_t)(wn * 32 + ((lane >> 4) & 1) * 8 + (lane & 7)) * 128;

    float acc[4][4][4];
#pragma unroll
    for (int mt = 0; mt < 4; mt++)
#pragma unroll
        for (int nt = 0; nt < 4; nt++)
#pragma unroll
            for (int v = 0; v < 4; v++) acc[mt][nt][v] = 0.f;

    for (int c = 0; c < KITER; c++) {
        CP_WAIT(NPIPE - 2);
        __syncthreads();
        if (c + NPIPE - 1 < KITER) ISSUE(c + NPIPE - 1);
        CP_COMMIT();

        uint32_t stb = sb + (c % NPIPE) * STAGE_B;
#pragma unroll
        for (int kt = 0; kt < 4; kt++) {
            unsigned af[4][4], bf[4][2];
#pragma unroll
            for (int mt = 0; mt < 4; mt++) {
                uint32_t ad = stb + aByte + mt * 2048 +
                              (uint32_t)(((2 * kt + aChunkBit) ^ s) << 4);
                LDSM_X4(af[mt][0], af[mt][1], af[mt][2], af[mt][3], ad);
            }
#pragma unroll
            for (int p = 0; p < 2; p++) {
                uint32_t bd = stb + bByte + p * 2048 +
                              (uint32_t)(((2 * kt + bChunkBit) ^ s) << 4);
                LDSM_X4(bf[2 * p][0], bf[2 * p][1], bf[2 * p + 1][0],
                        bf[2 * p + 1][1], bd);
            }
#pragma unroll
            for (int mt = 0; mt < 4; mt++)
#pragma unroll
                for (int nt = 0; nt < 4; nt++)
                    mma16816(acc[mt][nt], af[mt], bf[nt]);
        }
    }
#undef ISSUE

    // ---- epilogue ----
    int g = lane >> 2, tig = lane & 3;
#pragma unroll
    for (int mt = 0; mt < 4; mt++) {
#pragma unroll
        for (int hh = 0; hh < 2; hh++) {
            int r = wm * 64 + mt * 16 + g + 8 * hh;
            int slot = m0 + r;
            if (slot >= cnt) continue;
            if (MODE == 1) {
                __half* orow = g_h + (size_t)(off + slot) * HDIM + n0;
                const float* bp = bias + e * HDIM + n0;
#pragma unroll
                for (int nt = 0; nt < 4; nt++) {
                    int col = wn * 32 + nt * 8 + 2 * tig;
                    float v0 = fmaxf(acc[mt][nt][hh * 2 + 0] + bp[col], 0.f);
                    float v1 = fmaxf(acc[mt][nt][hh * 2 + 1] + bp[col + 1], 0.f);
                    __half2 hv = __floats2half2_rn(v0, v1);
                    *(__half2*)(orow + col) = hv;
                }
            } else {
                int tok = sRow[r] >> 1;
                float gte = sGate[r];
                float* orow = outp + (size_t)tok * DDIM + n0;
                const float* bp = bias + e * DDIM + n0;
#pragma unroll
                for (int nt = 0; nt < 4; nt++) {
                    int col = wn * 32 + nt * 8 + 2 * tig;
                    float v0 = acc[mt][nt][hh * 2 + 0];
                    float v1 = acc[mt][nt][hh * 2 + 1];
                    if (kz == 0) { v0 += bp[col]; v1 += bp[col + 1]; }
                    REDADD(orow + col, v0 * gte);
                    REDADD(orow + col + 1, v1 * gte);
                }
            }
        }
    }
}

// ---------------- launch -----------------------------------------------------
extern "C" void kernel_launch(void* const* d_in, const int* in_sizes, int n_in,
                              void* d_out, int out_size) {
    const float* x  = (const float*)d_in[0];
    const float* Wr = (const float*)d_in[1];
    const float* br = (const float*)d_in[2];
    const float* W1 = (const float*)d_in[3];
    const float* b1 = (const float*)d_in[4];
    const float* W2 = (const float*)d_in[5];
    const float* b2 = (const float*)d_in[6];
    float* out = (float*)d_out;
    (void)in_sizes; (void)n_in; (void)out_size;

    cudaFuncSetAttribute(moe_hgemm<16, 1>,
                         cudaFuncAttributeMaxDynamicSharedMemorySize, SMEM_BYTES);
    cudaFuncSetAttribute(moe_hgemm<32, 2>,
                         cudaFuncAttributeMaxDynamicSharedMemorySize, SMEM_BYTES);

    __half *xh, *w1h, *w2h;
    cudaGetSymbolAddress((void**)&xh, g_xh);
    cudaGetSymbolAddress((void**)&w1h, g_w1h);
    cudaGetSymbolAddress((void**)&w2h, g_w2h);

    {
        int n8 = NEXP * HDIM * DDIM / 8;
        int nz4 = NTOK * DDIM / 4;   // zero d_out (poisoned by harness)
        cvt_kernel<1><<<(n8 + 255) / 256, 256>>>(W1, w1h, n8, nullptr, 0);
        cvt_kernel<0><<<(n8 + 255) / 256, 256>>>(W2, w2h, n8, out, nz4);
    }
    router_kernel<<<NTOK / 8, 256>>>(x, Wr, br);   // also converts x

    dim3 g1(HDIM / TN, NTOK / TM, NEXP);        // 32 x 32 x 8
    moe_hgemm<16, 1><<<g1, 256, SMEM_BYTES>>>(xh, w1h, b1, nullptr);

    dim3 g2(DDIM / TN, NTOK / TM, NEXP * 2);    // 8 x 32 x 16 (split-K=2)
    moe_hgemm<32, 2><<<g2, 256, SMEM_BYTES>>>(nullptr, w2h, b2, out);
}

// round 17
// speedup vs baseline: 1.5105x; 1.0102x over previous
#include <cuda_runtime.h>
#include <cuda_fp16.h>
#include <math.h>
#include <stdint.h>

// Problem constants
#define NTOK 4096
#define DDIM 1024
#define HDIM 4096
#define NEXP 8
#define CAP  4096
#define NSLOT (NTOK*2)

// fp16 GEMM tiling: block 128x128, warp 64x32 (2x4 warps), K-chunk 64 (128B rows)
#define TM 128
#define TN 128
#define BKH 64
#define NPIPE 3
#define ASTAGE_B (TM*128)
#define BSTAGE_B (TN*128)
#define STAGE_B  (ASTAGE_B+BSTAGE_B)
#define SMEM_BYTES (NPIPE*STAGE_B)   // 98304 B -> 2 CTAs/SM

// ---------------- scratch ----------------------------------------------------
__device__ int    g_cnt[NEXP];
__device__ int    g_etok[NEXP * CAP];
__device__ float  g_egate[NEXP * CAP];
__device__ __half g_xh[(size_t)NTOK * DDIM];
__device__ __half g_w1h[(size_t)NEXP * HDIM * DDIM];
__device__ __half g_w2h[(size_t)NEXP * DDIM * HDIM];
__device__ __half g_h[(size_t)NSLOT * HDIM];

// ---------------- helpers ----------------------------------------------------
__device__ __forceinline__ uint32_t smem_u32(const void* p) {
    uint32_t a;
    asm("{ .reg .u64 t; cvta.to.shared.u64 t, %1; cvt.u32.u64 %0, t; }"
        : "=r"(a) : "l"(p));
    return a;
}
__device__ __forceinline__ void mma16816(float c[4], const unsigned a[4],
                                         const unsigned b[2]) {
    asm volatile(
        "mma.sync.aligned.m16n8k16.row.col.f32.f16.f16.f32 "
        "{%0,%1,%2,%3}, {%4,%5,%6,%7}, {%8,%9}, {%0,%1,%2,%3};"
        : "+f"(c[0]), "+f"(c[1]), "+f"(c[2]), "+f"(c[3])
        : "r"(a[0]), "r"(a[1]), "r"(a[2]), "r"(a[3]), "r"(b[0]), "r"(b[1]));
}
#define LDSM_X4(r0, r1, r2, r3, addr)                                        \
    asm volatile("ldmatrix.sync.aligned.m8n8.x4.shared.b16 {%0,%1,%2,%3}, [%4];" \
                 : "=r"(r0), "=r"(r1), "=r"(r2), "=r"(r3) : "r"(addr))
#define CPASYNC16(dst, src) \
    asm volatile("cp.async.cg.shared.global [%0], [%1], 16;" \
                 :: "r"(dst), "l"(src) : "memory")
#define CP_COMMIT() asm volatile("cp.async.commit_group;" ::: "memory")
#define CP_WAIT(n)  asm volatile("cp.async.wait_group %0;" :: "n"(n) : "memory")
#define REDADD(ptr, v) \
    asm volatile("red.global.add.f32 [%0], %1;" :: "l"(ptr), "f"(v) : "memory")

// ---------------- merged cvt kernel: W1 + W2 + zero(out) + init(g_cnt) -------
__global__ __launch_bounds__(256) void cvt2_kernel(
    const float* __restrict__ in1, __half* __restrict__ out1,
    const float* __restrict__ in2, __half* __restrict__ out2,
    int n8, float* __restrict__ zbuf, int nz4) {
    int i = blockIdx.x * 256 + threadIdx.x;
    if (i < NEXP) g_cnt[i] = 0;
    if (i < nz4) ((float4*)zbuf)[i] = make_float4(0.f, 0.f, 0.f, 0.f);
    const float* in;
    __half* out;
    int j;
    if (i < n8) { in = in1; out = out1; j = i; }
    else if (i < 2 * n8) { in = in2; out = out2; j = i - n8; }
    else return;
    size_t base = (size_t)j * 8;
    float4 v0 = *(const float4*)(in + base);
    float4 v1 = *(const float4*)(in + base + 4);
    __half2 h0 = __floats2half2_rn(v0.x, v0.y);
    __half2 h1 = __floats2half2_rn(v0.z, v0.w);
    __half2 h2 = __floats2half2_rn(v1.x, v1.y);
    __half2 h3 = __floats2half2_rn(v1.z, v1.w);
    uint4 u;
    u.x = *(uint32_t*)&h0; u.y = *(uint32_t*)&h1;
    u.z = *(uint32_t*)&h2; u.w = *(uint32_t*)&h3;
    *(uint4*)(out + base) = u;
}

// ---------------- router (fp32-exact) + x->fp16, CTA-aggregated atomics ------
__global__ __launch_bounds__(256) void router_kernel(
    const float* __restrict__ x, const float* __restrict__ Wr,
    const float* __restrict__ br) {
    __shared__ float sWr[NEXP * DDIM];
    __shared__ int sCnt[NEXP];
    __shared__ int sBase[NEXP];
    int tid = threadIdx.x;
    if (tid < NEXP) sCnt[tid] = 0;
    for (int i = tid; i < NEXP * DDIM; i += 256) sWr[i] = Wr[i];
    __syncthreads();
    int warp = tid >> 5, lane = tid & 31;
    int tok = blockIdx.x * 8 + warp;
    const float* xr = x + (size_t)tok * DDIM;
    __half* xo = g_xh + (size_t)tok * DDIM;
    float acc[NEXP];
#pragma unroll
    for (int e = 0; e < NEXP; e++) acc[e] = 0.f;
#pragma unroll
    for (int i = 0; i < DDIM / 128; i++) {
        int d = i * 128 + lane * 4;
        float4 xv = *(const float4*)(xr + d);
        __half2 h0 = __floats2half2_rn(xv.x, xv.y);
        __half2 h1 = __floats2half2_rn(xv.z, xv.w);
        uint2 u;
        u.x = *(uint32_t*)&h0; u.y = *(uint32_t*)&h1;
        *(uint2*)(xo + d) = u;
#pragma unroll
        for (int e = 0; e < NEXP; e++) {
            const float* w = sWr + e * DDIM + d;
            acc[e] += xv.x * w[0] + xv.y * w[1] + xv.z * w[2] + xv.w * w[3];
        }
    }
#pragma unroll
    for (int e = 0; e < NEXP; e++)
#pragma unroll
        for (int o = 16; o > 0; o >>= 1)
            acc[e] += __shfl_down_sync(0xffffffffu, acc[e], o);

    int i0 = 0, i1 = 0, p0loc = 0, p1loc = 0;
    float g0 = 0.f, g1 = 0.f;
    if (lane == 0) {
        float v0 = -3.4e38f, v1 = -3.4e38f;
#pragma unroll
        for (int e = 0; e < NEXP; e++) {
            float l = acc[e] + br[e];
            if (l > v0) { v1 = v0; i1 = i0; v0 = l; i0 = e; }
            else if (l > v1) { v1 = l; i1 = e; }
        }
        float t = expf(v1 - v0);
        float inv = 1.f / (1.f + t);
        g0 = inv;
        g1 = t * inv;
        p0loc = atomicAdd(&sCnt[i0], 1);
        p1loc = atomicAdd(&sCnt[i1], 1);
    }
    __syncthreads();
    if (tid < NEXP) sBase[tid] = atomicAdd(&g_cnt[tid], sCnt[tid]);
    __syncthreads();
    if (lane == 0) {
        int p0 = sBase[i0] + p0loc;
        g_etok[i0 * CAP + p0] = tok * 2;
        g_egate[i0 * CAP + p0] = g0;
        int p1 = sBase[i1] + p1loc;
        g_etok[i1 * CAP + p1] = tok * 2 + 1;
        g_egate[i1 * CAP + p1] = g1;
    }
}

// ---------------- fp16 grouped GEMM (R6 config: 8 warps, warp tile 64x32) -----
// MODE 1: g_h(fp16) = relu(gather(g_xh) @ g_w1h[e]^T + b1[e])   KITER=16, kz=0
// MODE 2: out += gate*(g_h @ g_w2h[e]^T [+ b2]) via red.global  KITER=32, kz=0,1
template <int KITER, int MODE>
__global__ __launch_bounds__(256, 2) void moe_hgemm(
    const __half* __restrict__ Ah, const __half* __restrict__ Bh,
    const float* __restrict__ bias, float* __restrict__ outp) {
    const int NTOT = (MODE == 1) ? HDIM : DDIM;
    const int KFULL = (MODE == 1) ? DDIM : HDIM;
    int z = blockIdx.z;
    int e = z & 7, kz = (MODE == 2) ? (z >> 3) : 0;
    int cnt = g_cnt[e];
    int m0 = blockIdx.y * TM;
    if (m0 >= cnt) return;
    int n0 = blockIdx.x * TN;
    int off = 0;
#pragma unroll
    for (int q = 0; q < NEXP; q++) off += (q < e) ? g_cnt[q] : 0;
    int k0g = kz * (KITER * BKH);

    extern __shared__ __align__(1024) char sm[];
    __shared__ int sRow[TM];
    __shared__ float sGate[TM];

    int tid = threadIdx.x;
    for (int r = tid; r < TM; r += 256) {
        int slot = m0 + r;
        if (MODE == 1) {
            sRow[r] = (slot < cnt) ? (g_etok[e * CAP + slot] >> 1) : 0;
        } else {
            sRow[r] = (slot < cnt) ? g_etok[e * CAP + slot] : 0;
            sGate[r] = (slot < cnt) ? g_egate[e * CAP + slot] : 0.f;
        }
    }
    __syncthreads();

    // ---- producer mapping: thread -> (row = tid/2, 4 of 8 16B chunks) ----
    int prow = tid >> 1;
    int c0 = (tid & 1) * 4;
    int psw = prow & 7;
    const __half* aRow;
    if (MODE == 1) {
        aRow = Ah + (size_t)sRow[prow] * KFULL + k0g;
    } else {
        int sg = off + m0 + prow;
        if (sg > NSLOT - 1) sg = NSLOT - 1;
        aRow = g_h + (size_t)sg * KFULL + k0g;
    }
    const __half* bRow = Bh + (size_t)e * NTOT * KFULL +
                         (size_t)(n0 + prow) * KFULL + k0g;
    uint32_t sb = smem_u32(sm);
    uint32_t aDstBase = sb + prow * 128;
    uint32_t bDstBase = sb + ASTAGE_B + prow * 128;

#define ISSUE(c)                                                      \
    {                                                                 \
        uint32_t so_ = ((c) % NPIPE) * STAGE_B;                       \
        const __half* ag_ = aRow + (c)*BKH;                           \
        const __half* bg_ = bRow + (c)*BKH;                           \
        _Pragma("unroll")                                             \
        for (int j = 0; j < 4; j++) {                                 \
            int cc = c0 + j;                                          \
            int sc = cc ^ psw;                                        \
            CPASYNC16(aDstBase + so_ + sc * 16, ag_ + cc * 8);        \
            CPASYNC16(bDstBase + so_ + sc * 16, bg_ + cc * 8);        \
        }                                                             \
    }

#pragma unroll
    for (int c = 0; c < NPIPE - 1; c++) {
        ISSUE(c);
        CP_COMMIT();
    }

    // ---- consumer mapping: 8 warps = 2(m) x 4(n), warp tile 64x32 ----
    int lane = tid & 31, wid = tid >> 5;
    int wm = wid >> 2, wn = wid & 3;
    int s = lane & 7;
    int aChunkBit = lane >> 4;
    uint32_t aByte = (uint32_t)(wm * 64 + (lane & 7) + ((lane >> 3) & 1) * 8) * 128;
    int bChunkBit = (lane >> 3) & 1;
    uint32_t bByte = ASTAGE_B +
                     (uint32_t)(wn * 32 + ((lane >> 4) & 1) * 8 + (lane & 7)) * 128;

    float acc[4][4][4];
#pragma unroll
    for (int mt = 0; mt < 4; mt++)
#pragma unroll
        for (int nt = 0; nt < 4; nt++)
#pragma unroll
            for (int v = 0; v < 4; v++) acc[mt][nt][v] = 0.f;

    for (int c = 0; c < KITER; c++) {
        CP_WAIT(NPIPE - 2);
        __syncthreads();
        if (c + NPIPE - 1 < KITER) ISSUE(c + NPIPE - 1);
        CP_COMMIT();

        uint32_t stb = sb + (c % NPIPE) * STAGE_B;
#pragma unroll
        for (int kt = 0; kt < 4; kt++) {
            unsigned af[4][4], bf[4][2];
#pragma unroll
            for (int mt = 0; mt < 4; mt++) {
                uint32_t ad = stb + aByte + mt * 2048 +
                              (uint32_t)(((2 * kt + aChunkBit) ^ s) << 4);
                LDSM_X4(af[mt][0], af[mt][1], af[mt][2], af[mt][3], ad);
            }
#pragma unroll
            for (int p = 0; p < 2; p++) {
                uint32_t bd = stb + bByte + p * 2048 +
                              (uint32_t)(((2 * kt + bChunkBit) ^ s) << 4);
                LDSM_X4(bf[2 * p][0], bf[2 * p][1], bf[2 * p + 1][0],
                        bf[2 * p + 1][1], bd);
            }
#pragma unroll
            for (int mt = 0; mt < 4; mt++)
#pragma unroll
                for (int nt = 0; nt < 4; nt++)
                    mma16816(acc[mt][nt], af[mt], bf[nt]);
        }
    }
#undef ISSUE

    // ---- epilogue ----
    int g = lane >> 2, tig = lane & 3;
#pragma unroll
    for (int mt = 0; mt < 4; mt++) {
#pragma unroll
        for (int hh = 0; hh < 2; hh++) {
            int r = wm * 64 + mt * 16 + g + 8 * hh;
            int slot = m0 + r;
            if (slot >= cnt) continue;
            if (MODE == 1) {
                __half* orow = g_h + (size_t)(off + slot) * HDIM + n0;
                const float* bp = bias + e * HDIM + n0;
#pragma unroll
                for (int nt = 0; nt < 4; nt++) {
                    int col = wn * 32 + nt * 8 + 2 * tig;
                    float v0 = fmaxf(acc[mt][nt][hh * 2 + 0] + bp[col], 0.f);
                    float v1 = fmaxf(acc[mt][nt][hh * 2 + 1] + bp[col + 1], 0.f);
                    __half2 hv = __floats2half2_rn(v0, v1);
                    *(__half2*)(orow + col) = hv;
                }
            } else {
                int tok = sRow[r] >> 1;
                float gte = sGate[r];
                float* orow = outp + (size_t)tok * DDIM + n0;
                const float* bp = bias + e * DDIM + n0;
#pragma unroll
                for (int nt = 0; nt < 4; nt++) {
                    int col = wn * 32 + nt * 8 + 2 * tig;
                    float v0 = acc[mt][nt][hh * 2 + 0];
                    float v1 = acc[mt][nt][hh * 2 + 1];
                    if (kz == 0) { v0 += bp[col]; v1 += bp[col + 1]; }
                    REDADD(orow + col, v0 * gte);
                    REDADD(orow + col + 1, v1 * gte);
                }
            }
        }
    }
}

// ---------------- launch -----------------------------------------------------
extern "C" void kernel_launch(void* const* d_in, const int* in_sizes, int n_in,
                              void* d_out, int out_size) {
    const float* x  = (const float*)d_in[0];
    const float* Wr = (const float*)d_in[1];
    const float* br = (const float*)d_in[2];
    const float* W1 = (const float*)d_in[3];
    const float* b1 = (const float*)d_in[4];
    const float* W2 = (const float*)d_in[5];
    const float* b2 = (const float*)d_in[6];
    float* out = (float*)d_out;
    (void)in_sizes; (void)n_in; (void)out_size;

    cudaFuncSetAttribute(moe_hgemm<16, 1>,
                         cudaFuncAttributeMaxDynamicSharedMemorySize, SMEM_BYTES);
    cudaFuncSetAttribute(moe_hgemm<32, 2>,
                         cudaFuncAttributeMaxDynamicSharedMemorySize, SMEM_BYTES);

    __half *xh, *w1h, *w2h;
    cudaGetSymbolAddress((void**)&xh, g_xh);
    cudaGetSymbolAddress((void**)&w1h, g_w1h);
    cudaGetSymbolAddress((void**)&w2h, g_w2h);

    {
        int n8 = NEXP * HDIM * DDIM / 8;
        int nz4 = NTOK * DDIM / 4;   // zero d_out (poisoned by harness)
        cvt2_kernel<<<(2 * n8 + 255) / 256, 256>>>(W1, w1h, W2, w2h, n8,
                                                   out, nz4);
    }
    router_kernel<<<NTOK / 8, 256>>>(x, Wr, br);   // also converts x

    dim3 g1(HDIM / TN, NTOK / TM, NEXP);        // 32 x 32 x 8
    moe_hgemm<16, 1><<<g1, 256, SMEM_BYTES>>>(xh, w1h, b1, nullptr);

    dim3 g2(DDIM / TN, NTOK / TM, NEXP * 2);    // 8 x 32 x 16 (split-K=2)
    moe_hgemm<32, 2><<<g2, 256, SMEM_BYTES>>>(nullptr, w2h, b2, out);
}